// round 13
// baseline (speedup 1.0000x reference)
#include <cuda_runtime.h>
#include <math.h>

// Problem constants
#define BB   2
#define AA   3
#define NCLS 3
#define CC   (NCLS*AA)   // 9 channels
#define DD   64
#define HH   128
#define WW   128
#define MM   128
#define EPSF 1e-4f

#define HT     8                 // h rows per block (one warp per row)
#define DSPLIT 4
#define DCHUNK (DD/DSPLIT)       // 16 d-slices per block
#define NWARP  HT                // 8 warps / block
#define HHWW   (HH*WW)

#define HTILES (HH/HT)           // 16
#define NEG_BLOCKS (BB * CC * HTILES * DSPLIT)   // 1152

#define NEG_INF __int_as_float(0xff800000)

__device__ __forceinline__ float warp_sum(float v) {
    #pragma unroll
    for (int o = 16; o; o >>= 1) v += __shfl_down_sync(0xffffffffu, v, o);
    return v;
}

__device__ __forceinline__ float4 fmax4(float4 a, float4 b) {
    return make_float4(fmaxf(a.x, b.x), fmaxf(a.y, b.y),
                       fmaxf(a.z, b.z), fmaxf(a.w, b.w));
}

// w-direction 3-window max of a row held as float4 per lane (warp-wide row).
__device__ __forceinline__ float4 wmax3(float4 v, int lane) {
    float left  = __shfl_up_sync(0xffffffffu, v.w, 1);
    float right = __shfl_down_sync(0xffffffffu, v.x, 1);
    if (lane == 0)  left  = NEG_INF;
    if (lane == 31) right = NEG_INF;
    float4 r;
    r.x = fmaxf(fmaxf(left, v.x), v.y);
    r.y = fmaxf(fmaxf(v.x, v.y), v.z);
    r.z = fmaxf(fmaxf(v.y, v.z), v.w);
    r.w = fmaxf(fmaxf(v.z, v.w), right);
    return r;
}

__global__ __launch_bounds__(32 * NWARP, 6)
void focal_kernel(const float* __restrict__ logits,
                  const float* __restrict__ prob_gt,
                  const int* __restrict__ coord,
                  const float* __restrict__ wcls,
                  float* __restrict__ out)
{
    const int lane = threadIdx.x;             // 0..31 (w4)
    const int ty   = threadIdx.y;             // 0..7 (h row within tile)
    const int tid  = ty * 32 + lane;
    const int gid  = blockIdx.x;

    // ======================= POS / OTHER path (one block) ===================
    if (gid == NEG_BLOCKS) {
        __shared__ int   present[BB][NCLS];
        __shared__ float rp0[NWARP], rp1[NWARP], rp2[NWARP], rp3[NWARP];

        if (tid < BB * NCLS) present[tid / NCLS][tid % NCLS] = 0;
        __syncthreads();

        const int b = tid >> 7;               // 256 threads = BB*MM exactly
        const int m = tid & (MM - 1);

        const int* cg = coord + ((size_t)b * MM + m) * 4;
        const int c0 = cg[0];
        const bool valid = c0 > -1;
        const int a = valid ? c0    : 0;
        const int d = valid ? cg[1] : 0;
        const int h = valid ? cg[2] : 0;
        const int w = valid ? cg[3] : 0;
        const float pgv = prob_gt[(((size_t)(b * AA + a) * DD + d) * HH + h) * WW + w];
        int cls = valid ? ((int)pgv - 1) : 0;
        cls = min(max(cls, 0), NCLS - 1);
        if (valid) present[b][cls] = 1;       // benign race
        __syncthreads();

        const float vf = valid ? 1.0f : 0.0f;
        auto getp = [&](int ch) -> float {
            const float x = logits[(((size_t)(b * CC + ch) * DD + d) * HH + h) * WW + w];
            float p = 1.0f / (1.0f + expf(-x));
            return fminf(fmaxf(p, EPSF), 1.0f - EPSF);
        };
        const float pt   = getp(cls * AA + a);
        const float omt  = 1.0f - pt;
        const float wpos = omt * omt * wcls[cls] * vf;
        float lpos = -logf(pt) * wpos;
        float cpos = wpos;

        float loth = 0.f, coth = 0.f;
        const float thr = pt - 0.1f;
        const float ptgate = (pt > 0.5f) ? 1.0f : 0.0f;
        #pragma unroll
        for (int k = 0; k < NCLS; ++k) {
            const float po = getp(k * AA + a);
            float wo = fmaxf(po - thr, 0.0f);
            wo *= (po > 0.5f) ? 1.0f : 0.0f;
            wo *= ptgate;
            if (present[b][k]) wo = 0.0f;
            wo *= vf;
            loth += -logf(1.0f - po) * wo;
            coth += wo;
        }

        const int wid = tid >> 5, ln = tid & 31;
        lpos = warp_sum(lpos); cpos = warp_sum(cpos);
        loth = warp_sum(loth); coth = warp_sum(coth);
        if (ln == 0) { rp0[wid] = lpos; rp1[wid] = cpos; rp2[wid] = loth; rp3[wid] = coth; }
        __syncthreads();
        if (tid == 0) {
            float s0 = 0, s1 = 0, s2 = 0, s3 = 0;
            #pragma unroll
            for (int i = 0; i < NWARP; ++i) { s0 += rp0[i]; s1 += rp1[i]; s2 += rp2[i]; s3 += rp3[i]; }
            atomicAdd(&out[0], s0);   // l_pos
            atomicAdd(&out[3], s1);   // c_pos
            atomicAdd(&out[2], s2);   // l_oth
            atomicAdd(&out[5], s3);   // c_oth
        }
        return;
    }

    // ============================ NEG path ==================================
    // gid in [0, 1152): bc = gid/64; t = gid%64 -> h tile (16) x d quarter (4)
    const int bc = gid >> 6;              // 0..17
    const int t  = gid & 63;
    const int b  = bc / CC;
    const int c  = bc % CC;
    const int a  = c % AA;                // negmask uses prob_gt[b, a]
    const int h0 = (t & 15) * HT;
    const int d0 = (t >> 4) * DCHUNK;

    const int h = h0 + ty;                // every warp produces output

    const float* chan = logits  + ((size_t)(b * CC + c) * DD * HH + h) * WW + lane * 4;
    const float* pgp  = prob_gt + ((size_t)(b * AA + a) * DD * HH + h) * WW + lane * 4;

    // 'SAME'-pool boundary clamp: duplicated edge row/plane == clipped window
    const int topoff = (h > 0)      ? -WW : 0;
    const int botoff = (h < HH - 1) ?  WW : 0;

    // ---- prologue ----
    float4 whm_m1, whm_0, ccur;
    {
        const float* base = chan + (size_t)max(d0 - 1, 0) * HHWW;
        float4 vm = fmax4(fmax4(*(const float4*)(base + topoff),
                                *(const float4*)(base)),
                          *(const float4*)(base + botoff));
        whm_m1 = wmax3(vm, lane);
        base = chan + (size_t)d0 * HHWW;
        float4 mm = *(const float4*)(base);
        ccur = mm;
        vm = fmax4(fmax4(*(const float4*)(base + topoff), mm),
                   *(const float4*)(base + botoff));
        whm_0 = wmax3(vm, lane);
    }
    // preload plane d0+1 rows (raw) and pg(d0)
    float4 nt, nm, nb;
    {
        const float* base = chan + (size_t)(d0 + 1) * HHWW;
        nt = *(const float4*)(base + topoff);
        nm = *(const float4*)(base);
        nb = *(const float4*)(base + botoff);
    }
    float4 pgc = *(const float4*)(pgp + (size_t)d0 * HHWW);

    float loss = 0.0f, cnt = 0.0f;

    #pragma unroll 2
    for (int d = d0; d < d0 + DCHUNK; ++d) {
        // finish plane d+1: vertical+horizontal max from preloaded rows
        const float4 whm_p1 = wmax3(fmax4(fmax4(nt, nm), nb), lane);
        const float4 cnext  = nm;

        // issue loads for plane d+2 (clamped at volume edge) and pg(d+1)
        {
            const float* base = chan + (size_t)min(d + 2, DD - 1) * HHWW;
            nt = *(const float4*)(base + topoff);
            nm = *(const float4*)(base);
            nb = *(const float4*)(base + botoff);
        }
        const float4 pgn = *(const float4*)(pgp + (size_t)min(d + 1, DD - 1) * HHWW);

        // 3x3x3 max for output plane d
        const float4 m = fmax4(fmax4(whm_m1, whm_0), whm_p1);

        {
            const bool b0 = (m.x == ccur.x) && (pgc.x == -1.0f);
            const bool b1 = (m.y == ccur.y) && (pgc.y == -1.0f);
            const bool b2 = (m.z == ccur.z) && (pgc.z == -1.0f);
            const bool b3 = (m.w == ccur.w) && (pgc.w == -1.0f);
            if (b0 | b1 | b2 | b3) {
                const bool  bb[4] = { b0, b1, b2, b3 };
                const float cc[4] = { ccur.x, ccur.y, ccur.z, ccur.w };
                #pragma unroll
                for (int i = 0; i < 4; ++i) {
                    if (bb[i]) {
                        float p = __fdividef(1.0f, 1.0f + __expf(-cc[i]));
                        p = fminf(fmaxf(p, EPSF), 1.0f - EPSF);
                        if (p > EPSF) {
                            const float w = p * p;      // p^ALPHA, ALPHA=2
                            loss -= __logf(1.0f - p) * w;
                            cnt  += w;
                        }
                    }
                }
            }
        }

        whm_m1 = whm_0;
        whm_0  = whm_p1;
        ccur   = cnext;
        pgc    = pgn;
    }

    // block reduction (8 warps)
    __shared__ float redl[NWARP], redc[NWARP];
    loss = warp_sum(loss);
    cnt  = warp_sum(cnt);
    if (lane == 0) { redl[ty] = loss; redc[ty] = cnt; }
    __syncthreads();
    if (tid == 0) {
        float l = 0.f, cv = 0.f;
        #pragma unroll
        for (int i = 0; i < NWARP; ++i) { l += redl[i]; cv += redc[i]; }
        atomicAdd(&out[1], l);    // loss_neg
        atomicAdd(&out[4], cv);   // count_neg
    }
}

extern "C" void kernel_launch(void* const* d_in, const int* in_sizes, int n_in,
                              void* d_out, int out_size)
{
    const float* logits  = (const float*)d_in[0];
    const float* prob_gt = (const float*)d_in[1];
    const int*   coord   = (const int*)d_in[2];
    const float* wcls    = (const float*)d_in[3];
    float* out = (float*)d_out;

    cudaMemsetAsync(out, 0, (size_t)out_size * sizeof(float));

    // 1D grid: 1152 neg work blocks + 1 pos block; 256 threads each
    focal_kernel<<<NEG_BLOCKS + 1, dim3(32, NWARP)>>>(logits, prob_gt, coord, wcls, out);
}

// round 14
// speedup vs baseline: 1.3316x; 1.3316x over previous
#include <cuda_runtime.h>
#include <math.h>

// Problem constants
#define BB   2
#define AA   3
#define NCLS 3
#define CC   (NCLS*AA)   // 9 channels
#define DD   64
#define HH   128
#define WW   128
#define MM   128
#define EPSF 1e-4f
#define ONE_M_EPS (1.0f - 1e-4f)

#define HT     8                 // h rows per block (one warp per row)
#define DSPLIT 4
#define DCHUNK (DD/DSPLIT)       // 16 d-slices per block
#define NWARP  HT                // 8 warps / block
#define HHWW   (HH*WW)

#define HTILES (HH/HT)           // 16
#define NEG_BLOCKS (BB * CC * HTILES * DSPLIT)   // 1152

#define NEG_INF __int_as_float(0xff800000)

__device__ __forceinline__ float warp_sum(float v) {
    #pragma unroll
    for (int o = 16; o; o >>= 1) v += __shfl_down_sync(0xffffffffu, v, o);
    return v;
}

__device__ __forceinline__ float4 fmax4(float4 a, float4 b) {
    return make_float4(fmaxf(a.x, b.x), fmaxf(a.y, b.y),
                       fmaxf(a.z, b.z), fmaxf(a.w, b.w));
}

// w-direction 3-window max of a row held as float4 per lane (warp-wide row).
__device__ __forceinline__ float4 wmax3(float4 v, int lane) {
    float left  = __shfl_up_sync(0xffffffffu, v.w, 1);
    float right = __shfl_down_sync(0xffffffffu, v.x, 1);
    if (lane == 0)  left  = NEG_INF;
    if (lane == 31) right = NEG_INF;
    float4 r;
    r.x = fmaxf(fmaxf(left, v.x), v.y);
    r.y = fmaxf(fmaxf(v.x, v.y), v.z);
    r.z = fmaxf(fmaxf(v.y, v.z), v.w);
    r.w = fmaxf(fmaxf(v.z, v.w), right);
    return r;
}

__global__ __launch_bounds__(32 * NWARP, 5)
void focal_kernel(const float* __restrict__ logits,
                  const float* __restrict__ prob_gt,
                  const int* __restrict__ coord,
                  const float* __restrict__ wcls,
                  float* __restrict__ out)
{
    const int lane = threadIdx.x;             // 0..31 (w4)
    const int ty   = threadIdx.y;             // 0..7 (h row within tile)
    const int tid  = ty * 32 + lane;
    const int gid  = blockIdx.x;

    // ======================= POS / OTHER path (one block) ===================
    if (gid == NEG_BLOCKS) {
        __shared__ int   present[BB][NCLS];
        __shared__ float rp0[NWARP], rp1[NWARP], rp2[NWARP], rp3[NWARP];

        if (tid < BB * NCLS) present[tid / NCLS][tid % NCLS] = 0;
        __syncthreads();

        const int b = tid >> 7;               // 256 threads = BB*MM exactly
        const int m = tid & (MM - 1);

        const int* cg = coord + ((size_t)b * MM + m) * 4;
        const int c0 = cg[0];
        const bool valid = c0 > -1;
        const int a = valid ? c0    : 0;
        const int d = valid ? cg[1] : 0;
        const int h = valid ? cg[2] : 0;
        const int w = valid ? cg[3] : 0;
        const float pgv = prob_gt[(((size_t)(b * AA + a) * DD + d) * HH + h) * WW + w];
        int cls = valid ? ((int)pgv - 1) : 0;
        cls = min(max(cls, 0), NCLS - 1);
        if (valid) present[b][cls] = 1;       // benign race
        __syncthreads();

        const float vf = valid ? 1.0f : 0.0f;
        auto getp = [&](int ch) -> float {
            const float x = logits[(((size_t)(b * CC + ch) * DD + d) * HH + h) * WW + w];
            float p = 1.0f / (1.0f + expf(-x));
            return fminf(fmaxf(p, EPSF), 1.0f - EPSF);
        };
        const float pt   = getp(cls * AA + a);
        const float omt  = 1.0f - pt;
        const float wpos = omt * omt * wcls[cls] * vf;
        float lpos = -logf(pt) * wpos;
        float cpos = wpos;

        float loth = 0.f, coth = 0.f;
        const float thr = pt - 0.1f;
        const float ptgate = (pt > 0.5f) ? 1.0f : 0.0f;
        #pragma unroll
        for (int k = 0; k < NCLS; ++k) {
            const float po = getp(k * AA + a);
            float wo = fmaxf(po - thr, 0.0f);
            wo *= (po > 0.5f) ? 1.0f : 0.0f;
            wo *= ptgate;
            if (present[b][k]) wo = 0.0f;
            wo *= vf;
            loth += -logf(1.0f - po) * wo;
            coth += wo;
        }

        const int wid = tid >> 5, ln = tid & 31;
        lpos = warp_sum(lpos); cpos = warp_sum(cpos);
        loth = warp_sum(loth); coth = warp_sum(coth);
        if (ln == 0) { rp0[wid] = lpos; rp1[wid] = cpos; rp2[wid] = loth; rp3[wid] = coth; }
        __syncthreads();
        if (tid == 0) {
            float s0 = 0, s1 = 0, s2 = 0, s3 = 0;
            #pragma unroll
            for (int i = 0; i < NWARP; ++i) { s0 += rp0[i]; s1 += rp1[i]; s2 += rp2[i]; s3 += rp3[i]; }
            atomicAdd(&out[0], s0);   // l_pos
            atomicAdd(&out[3], s1);   // c_pos
            atomicAdd(&out[2], s2);   // l_oth
            atomicAdd(&out[5], s3);   // c_oth
        }
        return;
    }

    // ============================ NEG path ==================================
    // gid in [0, 1152): bc = gid/64; t = gid%64 -> h tile (16) x d quarter (4)
    const int bc = gid >> 6;              // 0..17
    const int t  = gid & 63;
    const int b  = bc / CC;
    const int c  = bc % CC;
    const int a  = c % AA;                // negmask uses prob_gt[b, a]
    const int h0 = (t & 15) * HT;
    const int d0 = (t >> 4) * DCHUNK;

    const int h = h0 + ty;                // every warp produces output

    const float* chan = logits  + ((size_t)(b * CC + c) * DD * HH + h) * WW + lane * 4;
    const float* pgp  = prob_gt + ((size_t)(b * AA + a) * DD * HH + h) * WW + lane * 4;

    // 'SAME'-pool boundary clamp: duplicated edge row/plane == clipped window
    const int topoff = (h > 0)      ? -WW : 0;
    const int botoff = (h < HH - 1) ?  WW : 0;

    // ---- prologue ----
    float4 whm_m1, whm_0, ccur;
    {
        const float* base = chan + (size_t)max(d0 - 1, 0) * HHWW;
        float4 vm = fmax4(fmax4(*(const float4*)(base + topoff),
                                *(const float4*)(base)),
                          *(const float4*)(base + botoff));
        whm_m1 = wmax3(vm, lane);
        base = chan + (size_t)d0 * HHWW;
        float4 mm = *(const float4*)(base);
        ccur = mm;
        vm = fmax4(fmax4(*(const float4*)(base + topoff), mm),
                   *(const float4*)(base + botoff));
        whm_0 = wmax3(vm, lane);
    }
    // preload plane d0+1 rows (raw) and pg(d0)
    float4 nt, nm, nb;
    {
        const float* base = chan + (size_t)(d0 + 1) * HHWW;
        nt = *(const float4*)(base + topoff);
        nm = *(const float4*)(base);
        nb = *(const float4*)(base + botoff);
    }
    float4 pgc = *(const float4*)(pgp + (size_t)d0 * HHWW);

    // streaming pointers: logits plane d+2, pg plane d+1 (advance by SEL stride)
    const float* nptr = chan + (size_t)(d0 + 2) * HHWW;   // d0+2 <= 50 < DD, valid
    const float* gptr = pgp  + (size_t)(d0 + 1) * HHWW;   // valid

    float loss = 0.0f, cnt = 0.0f;

    #pragma unroll 4
    for (int d = d0; d < d0 + DCHUNK; ++d) {
        // issue streaming loads FIRST (consumed next iteration): max dep slack
        const float4 lt = *(const float4*)(nptr + topoff);
        const float4 lm = *(const float4*)(nptr);
        const float4 lb = *(const float4*)(nptr + botoff);
        const float4 pgn = *(const float4*)(gptr);
        nptr += (d + 3 < DD) ? HHWW : 0;    // next iter wants plane min(d+3, DD-1)
        gptr += (d + 2 < DD) ? HHWW : 0;    // next iter wants pg min(d+2, DD-1)

        // finish plane d+1: vertical+horizontal max from PREVIOUS iter's loads
        const float4 whm_p1 = wmax3(fmax4(fmax4(nt, nm), nb), lane);
        const float4 cnext  = nm;

        // 3x3x3 max for output plane d
        const float4 m = fmax4(fmax4(whm_m1, whm_0), whm_p1);

        {
            const bool b0 = (m.x == ccur.x) && (pgc.x == -1.0f);
            const bool b1 = (m.y == ccur.y) && (pgc.y == -1.0f);
            const bool b2 = (m.z == ccur.z) && (pgc.z == -1.0f);
            const bool b3 = (m.w == ccur.w) && (pgc.w == -1.0f);
            if (b0 | b1 | b2 | b3) {
                const bool  bb[4] = { b0, b1, b2, b3 };
                const float cc[4] = { ccur.x, ccur.y, ccur.z, ccur.w };
                #pragma unroll
                for (int i = 0; i < 4; ++i) {
                    if (bb[i]) {
                        const float p = __fdividef(1.0f, 1.0f + __expf(-cc[i]));
                        // low clamp subsumed by threshold test (sigma<=eps -> skip)
                        if (p > EPSF) {
                            const float pc = fminf(p, ONE_M_EPS);
                            const float w  = pc * pc;   // p^ALPHA, ALPHA=2
                            loss -= __logf(1.0f - pc) * w;
                            cnt  += w;
                        }
                    }
                }
            }
        }

        whm_m1 = whm_0;
        whm_0  = whm_p1;
        ccur   = cnext;
        pgc    = pgn;
        nt = lt; nm = lm; nb = lb;
    }

    // block reduction (8 warps)
    __shared__ float redl[NWARP], redc[NWARP];
    loss = warp_sum(loss);
    cnt  = warp_sum(cnt);
    if (lane == 0) { redl[ty] = loss; redc[ty] = cnt; }
    __syncthreads();
    if (tid == 0) {
        float l = 0.f, cv = 0.f;
        #pragma unroll
        for (int i = 0; i < NWARP; ++i) { l += redl[i]; cv += redc[i]; }
        atomicAdd(&out[1], l);    // loss_neg
        atomicAdd(&out[4], cv);   // count_neg
    }
}

extern "C" void kernel_launch(void* const* d_in, const int* in_sizes, int n_in,
                              void* d_out, int out_size)
{
    const float* logits  = (const float*)d_in[0];
    const float* prob_gt = (const float*)d_in[1];
    const int*   coord   = (const int*)d_in[2];
    const float* wcls    = (const float*)d_in[3];
    float* out = (float*)d_out;

    cudaMemsetAsync(out, 0, (size_t)out_size * sizeof(float));

    // 1D grid: 1152 neg work blocks + 1 pos block; 256 threads each
    focal_kernel<<<NEG_BLOCKS + 1, dim3(32, NWARP)>>>(logits, prob_gt, coord, wcls, out);
}